// round 1
// baseline (speedup 1.0000x reference)
#include <cuda_runtime.h>
#include <math.h>

#define Bb 64
#define LL 196
#define TT 32
#define MAXT 31
#define ED 2048
#define AD 512
#define DD 512
#define VV 10000
#define XK 3072
#define HSPLIT 8
#define GSPLIT 6

// d_out layout (float32): predictions, caps, dl, alphas, sort_idx
#define PRED_OFF  0
#define CAPS_OFF  (Bb*MAXT*VV)                 /* 19,840,000 */
#define DL_OFF    (CAPS_OFF + Bb*TT)
#define ALPHA_OFF (DL_OFF + Bb)
#define SIDX_OFF  (ALPHA_OFF + Bb*MAXT*LL)
#define OUT_TOT   (SIDX_OFF + Bb)

// ------------------- static device scratch (no runtime allocation) -------------------
__device__ int   g_sidx[Bb];
__device__ int   g_dl[Bb];
__device__ int   g_nb[MAXT];
__device__ float g_mean[Bb*ED];
__device__ float g_h[Bb*DD];
__device__ float g_c[Bb*DD];
__device__ float g_WaEnc[(size_t)Bb*LL*AD];        // 25.7 MB
__device__ float g_Wcat[(size_t)2048*XK];          // 25.2 MB  [W_ih | W_hh]
__device__ float g_hUpart[HSPLIT*Bb*AD];
__device__ float g_beta[Bb];
__device__ float g_energy[Bb*LL];
__device__ float g_xcat[Bb*XK];                    // [emb | context | h]
__device__ float g_gatesPart[GSPLIT*Bb*2048];

__device__ __forceinline__ float sigmoidf_(float x){ return 1.0f/(1.0f+expf(-x)); }

// ------------------- sort (stable descending argsort of lengths) -------------------
__global__ void k_sort(const int* __restrict__ lengths, const int* __restrict__ captions,
                       float* __restrict__ out)
{
    __shared__ int slen[Bb];
    __shared__ int sdl[Bb];
    int i = threadIdx.x;                 // 64 threads
    slen[i] = lengths[i];
    __syncthreads();
    int li = slen[i];
    int rank = 0;
    #pragma unroll 8
    for (int j = 0; j < Bb; j++) {
        int lj = slen[j];
        if (lj > li || (lj == li && j < i)) rank++;
    }
    g_sidx[rank] = i;
    __syncthreads();
    int src = g_sidx[i];
    int dl  = slen[src] - 1;
    g_dl[i] = dl;  sdl[i] = dl;
    out[DL_OFF + i]   = (float)dl;
    out[SIDX_OFF + i] = (float)src;
    for (int t2 = 0; t2 < TT; t2++)
        out[CAPS_OFF + i*TT + t2] = (float)captions[src*TT + t2];
    __syncthreads();
    if (i < MAXT) {
        int c = 0;
        for (int j = 0; j < Bb; j++) if (sdl[j] > i) c++;
        g_nb[i] = c;
    }
}

// ------------------- build Wcat = [W_ih (2048x2560) | W_hh (2048x512)] -------------------
__global__ void k_wcat(const float* __restrict__ W_ih, const float* __restrict__ W_hh)
{
    int j = blockIdx.x;          // 2048 rows
    for (int k = threadIdx.x; k < XK; k += 256)
        g_Wcat[(size_t)j*XK + k] = (k < 2560) ? W_ih[(size_t)j*2560 + k]
                                              : W_hh[(size_t)j*512 + (k - 2560)];
}

// ------------------- per-batch encoder mean (gathered) -------------------
__global__ void k_mean(const float* __restrict__ enc)
{
    int b = blockIdx.x;
    const float* p = enc + (size_t)g_sidx[b]*LL*ED;
    for (int e = threadIdx.x; e < ED; e += 256) {
        float s = 0.f;
        #pragma unroll 4
        for (int l = 0; l < LL; l++) s += p[(size_t)l*ED + e];
        g_mean[b*ED + e] = s * (1.0f/196.0f);
    }
}

// ------------------- generic tiled FP32 GEMM -------------------
// C[M,N] = act(A[M,K] * op(B) + bias)
// TRANSB=false: B is KxN row-major (ldb==N). TRANSB=true: B is NxK row-major (ldb==K).
// GATHER: A row r -> encoder row g_sidx[r/196]*196 + r%196
// gridDim.z = K-split count; partial z is written to C + z*M*ldc (caller provides buffer)
// ROWLIM: only store rows m < g_nb[t]
template<bool TRANSB, bool GATHER, bool BIAS, bool TANH_ACT, bool ROWLIM>
__global__ void gemm_k(const float* __restrict__ A, const float* __restrict__ Bm,
                       float* __restrict__ C, const float* __restrict__ bias,
                       int M, int N, int K, int lda, int ldc, int t)
{
    const int BM = 64, BN = 64, BK = 16;
    __shared__ float As[BK][BM];
    __shared__ float Bs[BK][BN];

    int bn = blockIdx.x * BN;
    int bm = blockIdx.y * BM;
    int kz = blockIdx.z;
    int kPer = K / gridDim.z;
    int k0 = kz * kPer, kEnd = k0 + kPer;
    C += (size_t)kz * (size_t)M * (size_t)ldc;

    int tid = threadIdx.x;               // 256
    int tx = tid & 15, ty = tid >> 4;
    int a_m = tid >> 2, a_k = (tid & 3) << 2;
    int b_kk = tid >> 4, b_n = (tid & 15) << 2;

    size_t arow;
    if (GATHER) {
        int r = bm + a_m;
        arow = ((size_t)(g_sidx[r / LL] * LL + (r % LL))) * (size_t)lda;
    } else {
        arow = (size_t)(bm + a_m) * (size_t)lda;
    }

    float acc[4][4];
    #pragma unroll
    for (int i = 0; i < 4; i++)
        #pragma unroll
        for (int j = 0; j < 4; j++) acc[i][j] = 0.f;

    for (int kk0 = k0; kk0 < kEnd; kk0 += BK) {
        float4 av = *(const float4*)(A + arow + kk0 + a_k);
        As[a_k+0][a_m] = av.x; As[a_k+1][a_m] = av.y;
        As[a_k+2][a_m] = av.z; As[a_k+3][a_m] = av.w;

        if (TRANSB) {
            float4 bv = *(const float4*)(Bm + (size_t)(bn + a_m)*(size_t)K + kk0 + a_k);
            Bs[a_k+0][a_m] = bv.x; Bs[a_k+1][a_m] = bv.y;
            Bs[a_k+2][a_m] = bv.z; Bs[a_k+3][a_m] = bv.w;
        } else {
            int n = bn + b_n;
            const float* brow = Bm + (size_t)(kk0 + b_kk)*(size_t)N;
            float4 bv;
            if (n + 3 < N) {
                bv = *(const float4*)(brow + n);
            } else {
                bv.x = (n   < N) ? brow[n]   : 0.f;
                bv.y = (n+1 < N) ? brow[n+1] : 0.f;
                bv.z = (n+2 < N) ? brow[n+2] : 0.f;
                bv.w = 0.f;
            }
            *(float4*)&Bs[b_kk][b_n] = bv;
        }
        __syncthreads();

        #pragma unroll
        for (int kk = 0; kk < BK; kk++) {
            float a0 = As[kk][ty*4+0], a1 = As[kk][ty*4+1];
            float a2 = As[kk][ty*4+2], a3 = As[kk][ty*4+3];
            float4 bv = *(const float4*)&Bs[kk][tx*4];
            acc[0][0] += a0*bv.x; acc[0][1] += a0*bv.y; acc[0][2] += a0*bv.z; acc[0][3] += a0*bv.w;
            acc[1][0] += a1*bv.x; acc[1][1] += a1*bv.y; acc[1][2] += a1*bv.z; acc[1][3] += a1*bv.w;
            acc[2][0] += a2*bv.x; acc[2][1] += a2*bv.y; acc[2][2] += a2*bv.z; acc[2][3] += a2*bv.w;
            acc[3][0] += a3*bv.x; acc[3][1] += a3*bv.y; acc[3][2] += a3*bv.z; acc[3][3] += a3*bv.w;
        }
        __syncthreads();
    }

    int rl = ROWLIM ? g_nb[t] : M;
    #pragma unroll
    for (int i = 0; i < 4; i++) {
        int m = bm + ty*4 + i;
        if (m >= rl) continue;
        #pragma unroll
        for (int j = 0; j < 4; j++) {
            int n = bn + tx*4 + j;
            if (n < N) {
                float v = acc[i][j];
                if (BIAS) v += bias[n];
                if (TANH_ACT) v = tanhf(v);
                C[(size_t)m*(size_t)ldc + n] = v;
            }
        }
    }
}

// ------------------- per-step: emb copy, h copy, beta -------------------
__global__ void k_prestep(const int* __restrict__ captions, const float* __restrict__ embT,
                          const float* __restrict__ fb_W, const float* __restrict__ fb_b, int t)
{
    int b = blockIdx.x;
    if (b >= g_nb[t]) return;
    int tid = threadIdx.x;               // 256
    __shared__ float sred[8];
    int cap = captions[g_sidx[b]*TT + t];
    if (tid < 128)
        ((float4*)(g_xcat + (size_t)b*XK))[tid] =
            ((const float4*)(embT + (size_t)cap*DD))[tid];
    else
        ((float4*)(g_xcat + (size_t)b*XK + 2560))[tid-128] =
            ((const float4*)(g_h + (size_t)b*DD))[tid-128];

    float s = g_h[b*DD + tid]       * fb_W[tid]
            + g_h[b*DD + 256 + tid] * fb_W[256 + tid];
    #pragma unroll
    for (int o = 16; o > 0; o >>= 1) s += __shfl_xor_sync(0xffffffffu, s, o);
    if ((tid & 31) == 0) sred[tid >> 5] = s;
    __syncthreads();
    if (tid == 0) {
        float tot = 0.f;
        #pragma unroll
        for (int w = 0; w < 8; w++) tot += sred[w];
        g_beta[b] = 1.0f / (1.0f + expf(-(tot + fb_b[0])));
    }
}

// ------------------- per-step: attention energies -------------------
__global__ void k_energy(const float* __restrict__ w_att, int t)
{
    int b = blockIdx.x;
    if (b >= g_nb[t]) return;
    int yc = blockIdx.y;                 // 0..3, 49 rows each
    int tid = threadIdx.x;               // 256
    __shared__ float sHU[AD];
    __shared__ float sW[AD];
    for (int a = tid; a < AD; a += 256) {
        float s = 0.f;
        #pragma unroll
        for (int ks = 0; ks < HSPLIT; ks++)
            s += g_hUpart[((size_t)ks*Bb + b)*AD + a];
        sHU[a] = s;
        sW[a]  = w_att[a];
    }
    __syncthreads();
    int warp = tid >> 5, lane = tid & 31;
    int lend = min(yc*49 + 49, LL);
    for (int li = yc*49 + warp; li < lend; li += 8) {
        const float* wa = g_WaEnc + ((size_t)b*LL + li)*AD;
        float acc = 0.f;
        for (int a = lane; a < AD; a += 32)
            acc += tanhf(wa[a] + sHU[a]) * sW[a];
        #pragma unroll
        for (int o = 16; o > 0; o >>= 1) acc += __shfl_xor_sync(0xffffffffu, acc, o);
        if (lane == 0) g_energy[b*LL + li] = acc;
    }
}

// ------------------- per-step: softmax (recomputed per block) + context + alpha out -------------------
__global__ void k_context(const float* __restrict__ enc, float* __restrict__ out, int t)
{
    int b = blockIdx.x;
    if (b >= g_nb[t]) return;
    int ec = blockIdx.y;                 // 0..7 -> 256 e's each
    int tid = threadIdx.x;
    __shared__ float sAl[LL];
    __shared__ float sred[8];

    float v = (tid < LL) ? g_energy[b*LL + tid] : -3.4e38f;
    float m = v;
    #pragma unroll
    for (int o = 16; o > 0; o >>= 1) m = fmaxf(m, __shfl_xor_sync(0xffffffffu, m, o));
    if ((tid & 31) == 0) sred[tid >> 5] = m;
    __syncthreads();
    if (tid < 8) {
        float mm = sred[tid];
        #pragma unroll
        for (int o = 4; o > 0; o >>= 1) mm = fmaxf(mm, __shfl_xor_sync(0xffu, mm, o));
        if (tid == 0) sred[0] = mm;
    }
    __syncthreads();
    float mx = sred[0];
    __syncthreads();

    float p = (tid < LL) ? expf(v - mx) : 0.f;
    float s = p;
    #pragma unroll
    for (int o = 16; o > 0; o >>= 1) s += __shfl_xor_sync(0xffffffffu, s, o);
    if ((tid & 31) == 0) sred[tid >> 5] = s;
    __syncthreads();
    if (tid < 8) {
        float ss = sred[tid];
        #pragma unroll
        for (int o = 4; o > 0; o >>= 1) ss += __shfl_xor_sync(0xffu, ss, o);
        if (tid == 0) sred[0] = ss;
    }
    __syncthreads();
    float alpha = p / sred[0];
    if (tid < LL) sAl[tid] = alpha;
    if (ec == 0 && tid < LL)
        out[ALPHA_OFF + ((size_t)b*MAXT + t)*LL + tid] = alpha;
    __syncthreads();

    int e = ec*256 + tid;
    const float* pe = enc + (size_t)g_sidx[b]*LL*ED + e;
    float acc = 0.f;
    #pragma unroll 4
    for (int l = 0; l < LL; l++) acc += sAl[l] * pe[(size_t)l*ED];
    g_xcat[(size_t)b*XK + 512 + e] = acc * g_beta[b];
}

// ------------------- per-step: gate reduce + LSTM pointwise + h/c update -------------------
__global__ void k_lstm(const float* __restrict__ b_ih, const float* __restrict__ b_hh, int t)
{
    int b = blockIdx.x;
    if (b >= g_nb[t]) return;
    int tid = threadIdx.x;               // 256
    #pragma unroll
    for (int jj = 0; jj < 2; jj++) {
        int j = tid + jj*256;
        float gi = b_ih[j]        + b_hh[j];
        float gf = b_ih[512 + j]  + b_hh[512 + j];
        float gg = b_ih[1024 + j] + b_hh[1024 + j];
        float go = b_ih[1536 + j] + b_hh[1536 + j];
        #pragma unroll
        for (int ks = 0; ks < GSPLIT; ks++) {
            const float* gp = g_gatesPart + ((size_t)ks*Bb + b)*2048;
            gi += gp[j]; gf += gp[512 + j]; gg += gp[1024 + j]; go += gp[1536 + j];
        }
        float i_ = sigmoidf_(gi);
        float f_ = sigmoidf_(gf);
        float g2 = tanhf(gg);
        float o_ = sigmoidf_(go);
        float c = f_ * g_c[b*DD + j] + i_ * g2;
        float h = o_ * tanhf(c);
        g_c[b*DD + j] = c;
        g_h[b*DD + j] = h;
    }
}

// ------------------- host -------------------
extern "C" void kernel_launch(void* const* d_in, const int* in_sizes, int n_in,
                              void* d_out_v, int out_size)
{
    const float* enc   = (const float*)d_in[0];
    const int*   caps  = (const int*)  d_in[1];
    const int*   lens  = (const int*)  d_in[2];
    const float* embT  = (const float*)d_in[3];
    const float* W_a   = (const float*)d_in[4];
    const float* U_a   = (const float*)d_in[5];
    const float* w_att = (const float*)d_in[6];
    const float* fb_W  = (const float*)d_in[7];
    const float* fb_b  = (const float*)d_in[8];
    const float* W_ih  = (const float*)d_in[9];
    const float* W_hh  = (const float*)d_in[10];
    const float* b_ih  = (const float*)d_in[11];
    const float* b_hh  = (const float*)d_in[12];
    const float* fc_W  = (const float*)d_in[13];
    const float* fc_b  = (const float*)d_in[14];
    const float* ih_W  = (const float*)d_in[15];
    const float* ih_b  = (const float*)d_in[16];
    const float* ic_W  = (const float*)d_in[17];
    const float* ic_b  = (const float*)d_in[18];
    float* out = (float*)d_out_v;

    void *pMean, *pH, *pC, *pWaEnc, *pWcat, *pHU, *pXcat, *pGates;
    cudaGetSymbolAddress(&pMean,  g_mean);
    cudaGetSymbolAddress(&pH,     g_h);
    cudaGetSymbolAddress(&pC,     g_c);
    cudaGetSymbolAddress(&pWaEnc, g_WaEnc);
    cudaGetSymbolAddress(&pWcat,  g_Wcat);
    cudaGetSymbolAddress(&pHU,    g_hUpart);
    cudaGetSymbolAddress(&pXcat,  g_xcat);
    cudaGetSymbolAddress(&pGates, g_gatesPart);

    // masked outputs must be zero; d_out is poisoned
    cudaMemsetAsync(out, 0, (size_t)out_size * sizeof(float), 0);

    k_sort<<<1, 64>>>(lens, caps, out);
    k_wcat<<<2048, 256>>>(W_ih, W_hh);
    k_mean<<<64, 256>>>(enc);

    // h0 = tanh(mean @ ih_W + ih_b), c0 = tanh(mean @ ic_W + ic_b)
    gemm_k<false,false,true,true,false><<<dim3(8,1,1), 256>>>(
        (const float*)pMean, ih_W, (float*)pH, ih_b, 64, 512, 2048, 2048, 512, 0);
    gemm_k<false,false,true,true,false><<<dim3(8,1,1), 256>>>(
        (const float*)pMean, ic_W, (float*)pC, ic_b, 64, 512, 2048, 2048, 512, 0);

    // Wa_enc = enc[sidx] @ W_a   (12544 x 512, K=2048)
    gemm_k<false,true,false,false,false><<<dim3(8,196,1), 256>>>(
        enc, W_a, (float*)pWaEnc, nullptr, 12544, 512, 2048, 2048, 512, 0);

    for (int t = 0; t < MAXT; t++) {
        k_prestep<<<64, 256>>>(caps, embT, fb_W, fb_b, t);

        // hU = h @ U_a   (K-split x8 -> partials, reduced in k_energy)
        gemm_k<false,false,false,false,false><<<dim3(8,1,HSPLIT), 256>>>(
            (const float*)pH, U_a, (float*)pHU, nullptr, 64, 512, 512, 512, 512, t);

        k_energy<<<dim3(64,4), 256>>>(w_att, t);
        k_context<<<dim3(64,8), 256>>>(enc, out, t);

        // gates = xcat @ Wcat^T   (K-split x6 -> partials, reduced in k_lstm)
        gemm_k<true,false,false,false,false><<<dim3(32,1,GSPLIT), 256>>>(
            (const float*)pXcat, (const float*)pWcat, (float*)pGates, nullptr,
            64, 2048, XK, XK, 2048, t);

        k_lstm<<<64, 256>>>(b_ih, b_hh, t);

        // pred = h_new @ fc_W + fc_b, written straight into d_out (row stride 31*V)
        gemm_k<false,false,true,false,true><<<dim3(157,1,1), 256>>>(
            (const float*)pH, fc_W, out + (size_t)t*VV, fc_b,
            64, VV, 512, 512, MAXT*VV, t);
    }
}

// round 2
// speedup vs baseline: 1.2846x; 1.2846x over previous
#include <cuda_runtime.h>
#include <math.h>

#define Bb 64
#define LL 196
#define TT 32
#define MAXT 31
#define ED 2048
#define AD 512
#define DD 512
#define VV 10000
#define XK 3072
#define HSPLIT 8
#define GSPLIT 12
#define FCLD 10112

// d_out layout (float32): predictions, caps, dl, alphas, sort_idx
#define PRED_OFF  0
#define CAPS_OFF  (Bb*MAXT*VV)
#define DL_OFF    (CAPS_OFF + Bb*TT)
#define ALPHA_OFF (DL_OFF + Bb)
#define SIDX_OFF  (ALPHA_OFF + Bb*MAXT*LL)

// ------------------- static device scratch -------------------
__device__ int   g_sidx[Bb];
__device__ int   g_nb[MAXT];
__device__ float g_mean[Bb*ED];
__device__ float g_h[Bb*DD];
__device__ float g_c[Bb*DD];
__device__ float g_WaEnc[(size_t)Bb*LL*AD];
__device__ float g_Wcat[(size_t)2048*XK];
__device__ float g_hUpart[HSPLIT*Bb*AD];
__device__ float g_beta[Bb];
__device__ float g_energy[Bb*LL];
__device__ float g_xcat[Bb*XK];                    // [emb | context | h]
__device__ float g_gatesPart[GSPLIT*Bb*2048];
__device__ float g_fcPart[2*Bb*FCLD];
__device__ float g_initPart[2*16*Bb*DD];

__device__ __forceinline__ float sigmoidf_(float x){ return 1.0f/(1.0f+expf(-x)); }

// ------------------- sort -------------------
__global__ void k_sort(const int* __restrict__ lengths, const int* __restrict__ captions,
                       float* __restrict__ out)
{
    __shared__ int slen[Bb];
    __shared__ int sdl[Bb];
    int i = threadIdx.x;
    slen[i] = lengths[i];
    __syncthreads();
    int li = slen[i];
    int rank = 0;
    #pragma unroll 8
    for (int j = 0; j < Bb; j++) {
        int lj = slen[j];
        if (lj > li || (lj == li && j < i)) rank++;
    }
    g_sidx[rank] = i;
    __syncthreads();
    int src = g_sidx[i];
    int dl  = slen[src] - 1;
    sdl[i] = dl;
    out[DL_OFF + i]   = (float)dl;
    out[SIDX_OFF + i] = (float)src;
    for (int t2 = 0; t2 < TT; t2++)
        out[CAPS_OFF + i*TT + t2] = (float)captions[src*TT + t2];
    __syncthreads();
    if (i < MAXT) {
        int c = 0;
        for (int j = 0; j < Bb; j++) if (sdl[j] > i) c++;
        g_nb[i] = c;
    }
}

// ------------------- build Wcat = [W_ih | W_hh] -------------------
__global__ void k_wcat(const float* __restrict__ W_ih, const float* __restrict__ W_hh)
{
    int j = blockIdx.x;
    for (int k = threadIdx.x; k < XK; k += 256)
        g_Wcat[(size_t)j*XK + k] = (k < 2560) ? W_ih[(size_t)j*2560 + k]
                                              : W_hh[(size_t)j*512 + (k - 2560)];
}

// ------------------- encoder mean -------------------
__global__ void k_mean(const float* __restrict__ enc)
{
    int b = blockIdx.x;
    int e = blockIdx.y*256 + threadIdx.x;
    const float* p = enc + (size_t)g_sidx[b]*LL*ED + e;
    float s = 0.f;
    #pragma unroll 4
    for (int l = 0; l < LL; l++) s += p[(size_t)l*ED];
    g_mean[b*ED + e] = s * (1.0f/196.0f);
}

// ------------------- FP32 GEMM: 64x128 tile, 4x8 per thread, reg prefetch -------------------
// C(partial z) = A[M,K] * op(B).  TRANSB=false: B KxN row-major. TRANSB=true: B NxK (N mult of 128).
// gridDim.z = K-split; partial z written at C + z*M*ldc.
template<bool TRANSB, bool GATHER>
__global__ void __launch_bounds__(256) gemm2(
    const float* __restrict__ A, const float* __restrict__ Bm,
    float* __restrict__ C, int M, int N, int K, int lda, int ldc)
{
    const int BM=64, BN=128, BK=16;
    __shared__ float As[BK][BM];
    __shared__ float Bs[BK][BN];
    int bn = blockIdx.x*BN, bm = blockIdx.y*BM;
    int kPer = K / gridDim.z;
    int k0 = blockIdx.z * kPer;
    int nIter = kPer / BK;
    C += (size_t)blockIdx.z * (size_t)M * (size_t)ldc;

    int tid = threadIdx.x;
    int tx = tid & 15, ty = tid >> 4;
    int a_m = tid >> 2, a_k = (tid & 3) << 2;
    int b_k = tid >> 4;            // 0..15
    int b_n = (tid & 15) << 2;     // 0..60
    int r2  = tid >> 2;            // 0..63

    size_t arow;
    if (GATHER) { int r = bm + a_m; arow = ((size_t)(g_sidx[r/LL]*LL + (r % LL)))*(size_t)lda; }
    else        { arow = (size_t)(bm + a_m)*(size_t)lda; }

    float4 aR, bR0, bR1;
    // prologue load
    {
        int kk0 = k0;
        aR = *(const float4*)(A + arow + kk0 + a_k);
        if (TRANSB) {
            bR0 = *(const float4*)(Bm + (size_t)(bn + r2)      * (size_t)K + kk0 + a_k);
            bR1 = *(const float4*)(Bm + (size_t)(bn + 64 + r2) * (size_t)K + kk0 + a_k);
        } else {
            const float* br = Bm + (size_t)(kk0 + b_k)*(size_t)N;
            int n0 = bn + b_n, n1 = bn + 64 + b_n;
            if (n0 + 3 < N) bR0 = *(const float4*)(br + n0);
            else { bR0.x = n0<N?br[n0]:0.f; bR0.y = n0+1<N?br[n0+1]:0.f;
                   bR0.z = n0+2<N?br[n0+2]:0.f; bR0.w = 0.f; }
            if (n1 + 3 < N) bR1 = *(const float4*)(br + n1);
            else { bR1.x = n1<N?br[n1]:0.f; bR1.y = n1+1<N?br[n1+1]:0.f;
                   bR1.z = n1+2<N?br[n1+2]:0.f; bR1.w = 0.f; }
        }
    }

    float acc[4][8];
    #pragma unroll
    for (int i = 0; i < 4; i++)
        #pragma unroll
        for (int j = 0; j < 8; j++) acc[i][j] = 0.f;

    for (int it = 0; it < nIter; it++) {
        // regs -> smem
        As[a_k+0][a_m] = aR.x; As[a_k+1][a_m] = aR.y;
        As[a_k+2][a_m] = aR.z; As[a_k+3][a_m] = aR.w;
        if (TRANSB) {
            Bs[a_k+0][r2] = bR0.x; Bs[a_k+1][r2] = bR0.y;
            Bs[a_k+2][r2] = bR0.z; Bs[a_k+3][r2] = bR0.w;
            Bs[a_k+0][64+r2] = bR1.x; Bs[a_k+1][64+r2] = bR1.y;
            Bs[a_k+2][64+r2] = bR1.z; Bs[a_k+3][64+r2] = bR1.w;
        } else {
            *(float4*)&Bs[b_k][b_n]      = bR0;
            *(float4*)&Bs[b_k][64 + b_n] = bR1;
        }
        __syncthreads();

        if (it + 1 < nIter) {
            int kk0 = k0 + (it+1)*BK;
            aR = *(const float4*)(A + arow + kk0 + a_k);
            if (TRANSB) {
                bR0 = *(const float4*)(Bm + (size_t)(bn + r2)      * (size_t)K + kk0 + a_k);
                bR1 = *(const float4*)(Bm + (size_t)(bn + 64 + r2) * (size_t)K + kk0 + a_k);
            } else {
                const float* br = Bm + (size_t)(kk0 + b_k)*(size_t)N;
                int n0 = bn + b_n, n1 = bn + 64 + b_n;
                if (n0 + 3 < N) bR0 = *(const float4*)(br + n0);
                else { bR0.x = n0<N?br[n0]:0.f; bR0.y = n0+1<N?br[n0+1]:0.f;
                       bR0.z = n0+2<N?br[n0+2]:0.f; bR0.w = 0.f; }
                if (n1 + 3 < N) bR1 = *(const float4*)(br + n1);
                else { bR1.x = n1<N?br[n1]:0.f; bR1.y = n1+1<N?br[n1+1]:0.f;
                       bR1.z = n1+2<N?br[n1+2]:0.f; bR1.w = 0.f; }
            }
        }

        #pragma unroll
        for (int kk = 0; kk < BK; kk++) {
            float4 av = *(const float4*)&As[kk][ty*4];
            float4 b0 = *(const float4*)&Bs[kk][tx*4];
            float4 b1 = *(const float4*)&Bs[kk][64 + tx*4];
            float a[4] = {av.x, av.y, av.z, av.w};
            #pragma unroll
            for (int i = 0; i < 4; i++) {
                acc[i][0] += a[i]*b0.x; acc[i][1] += a[i]*b0.y;
                acc[i][2] += a[i]*b0.z; acc[i][3] += a[i]*b0.w;
                acc[i][4] += a[i]*b1.x; acc[i][5] += a[i]*b1.y;
                acc[i][6] += a[i]*b1.z; acc[i][7] += a[i]*b1.w;
            }
        }
        __syncthreads();
    }

    // epilogue: cols [bn+tx*4 .. +3] and [bn+64+tx*4 .. +3]
    int n0 = bn + tx*4, n1 = bn + 64 + tx*4;
    #pragma unroll
    for (int i = 0; i < 4; i++) {
        int m = bm + ty*4 + i;
        float* cr = C + (size_t)m*(size_t)ldc;
        if (n0 + 3 < N) { *(float4*)(cr + n0) = *(float4*)&acc[i][0]; }
        else { for (int j = 0; j < 4; j++) if (n0 + j < N) cr[n0+j] = acc[i][j]; }
        if (n1 + 3 < N) { *(float4*)(cr + n1) = *(float4*)&acc[i][4]; }
        else { for (int j = 0; j < 4; j++) if (n1 + j < N) cr[n1+j] = acc[i][4+j]; }
    }
}

// ------------------- h0/c0 reduce + tanh -------------------
__global__ void k_init(const float* __restrict__ ih_b, const float* __restrict__ ic_b)
{
    int b = blockIdx.x;
    for (int j = threadIdx.x; j < DD; j += 256) {
        float sh = 0.f, sc = 0.f;
        #pragma unroll
        for (int ks = 0; ks < 16; ks++) {
            sh += g_initPart[((size_t)ks*Bb + b)*DD + j];
            sc += g_initPart[((size_t)(16+ks)*Bb + b)*DD + j];
        }
        g_h[b*DD + j] = tanhf(sh + ih_b[j]);
        g_c[b*DD + j] = tanhf(sc + ic_b[j]);
    }
}

// ------------------- energies + (folded) prestep: emb/h copy, beta -------------------
__global__ void k_energy(const int* __restrict__ captions, const float* __restrict__ embT,
                         const float* __restrict__ fb_W, const float* __restrict__ fb_b,
                         const float* __restrict__ w_att, int t)
{
    int b = blockIdx.x;
    if (b >= g_nb[t]) return;
    int yc = blockIdx.y;
    int tid = threadIdx.x;
    __shared__ float sHU[AD];
    __shared__ float sW[AD];
    __shared__ float sB[8];

    for (int a = tid; a < AD; a += 256) {
        float s = 0.f;
        #pragma unroll
        for (int ks = 0; ks < HSPLIT; ks++)
            s += g_hUpart[((size_t)ks*Bb + b)*AD + a];
        sHU[a] = s;
        sW[a]  = w_att[a];
    }

    if (yc == 0) {
        int cap = captions[g_sidx[b]*TT + t];
        if (tid < 128)
            ((float4*)(g_xcat + (size_t)b*XK))[tid] =
                ((const float4*)(embT + (size_t)cap*DD))[tid];
        else
            ((float4*)(g_xcat + (size_t)b*XK + 2560))[tid-128] =
                ((const float4*)(g_h + (size_t)b*DD))[tid-128];
        float s = g_h[b*DD + tid]       * fb_W[tid]
                + g_h[b*DD + 256 + tid] * fb_W[256 + tid];
        #pragma unroll
        for (int o = 16; o > 0; o >>= 1) s += __shfl_xor_sync(0xffffffffu, s, o);
        if ((tid & 31) == 0) sB[tid >> 5] = s;
    }
    __syncthreads();
    if (yc == 0 && tid == 0) {
        float tot = 0.f;
        #pragma unroll
        for (int w = 0; w < 8; w++) tot += sB[w];
        g_beta[b] = 1.0f / (1.0f + expf(-(tot + fb_b[0])));
    }

    int warp = tid >> 5, lane = tid & 31;
    int lend = min(yc*49 + 49, LL);
    for (int li = yc*49 + warp; li < lend; li += 8) {
        const float* wa = g_WaEnc + ((size_t)b*LL + li)*AD;
        float acc = 0.f;
        for (int a = lane; a < AD; a += 32)
            acc += tanhf(wa[a] + sHU[a]) * sW[a];
        #pragma unroll
        for (int o = 16; o > 0; o >>= 1) acc += __shfl_xor_sync(0xffffffffu, acc, o);
        if (lane == 0) g_energy[b*LL + li] = acc;
    }
}

// ------------------- softmax + context + alpha out -------------------
__global__ void k_context(const float* __restrict__ enc, float* __restrict__ out, int t)
{
    int b = blockIdx.x;
    if (b >= g_nb[t]) return;
    int ec = blockIdx.y;
    int tid = threadIdx.x;
    __shared__ float sAl[LL];
    __shared__ float sred[8];

    float v = (tid < LL) ? g_energy[b*LL + tid] : -3.4e38f;
    float m = v;
    #pragma unroll
    for (int o = 16; o > 0; o >>= 1) m = fmaxf(m, __shfl_xor_sync(0xffffffffu, m, o));
    if ((tid & 31) == 0) sred[tid >> 5] = m;
    __syncthreads();
    if (tid < 8) {
        float mm = sred[tid];
        #pragma unroll
        for (int o = 4; o > 0; o >>= 1) mm = fmaxf(mm, __shfl_xor_sync(0xffu, mm, o));
        if (tid == 0) sred[0] = mm;
    }
    __syncthreads();
    float mx = sred[0];
    __syncthreads();

    float p = (tid < LL) ? expf(v - mx) : 0.f;
    float s = p;
    #pragma unroll
    for (int o = 16; o > 0; o >>= 1) s += __shfl_xor_sync(0xffffffffu, s, o);
    if ((tid & 31) == 0) sred[tid >> 5] = s;
    __syncthreads();
    if (tid < 8) {
        float ss = sred[tid];
        #pragma unroll
        for (int o = 4; o > 0; o >>= 1) ss += __shfl_xor_sync(0xffu, ss, o);
        if (tid == 0) sred[0] = ss;
    }
    __syncthreads();
    float alpha = p / sred[0];
    if (tid < LL) sAl[tid] = alpha;
    if (ec == 0 && tid < LL)
        out[ALPHA_OFF + ((size_t)b*MAXT + t)*LL + tid] = alpha;
    __syncthreads();

    int e = ec*256 + tid;
    const float* pe = enc + (size_t)g_sidx[b]*LL*ED + e;
    float acc = 0.f;
    #pragma unroll 4
    for (int l = 0; l < LL; l++) acc += sAl[l] * pe[(size_t)l*ED];
    g_xcat[(size_t)b*XK + 512 + e] = acc * g_beta[b];
}

// ------------------- gate reduce + LSTM pointwise -------------------
__global__ void k_lstm(const float* __restrict__ b_ih, const float* __restrict__ b_hh, int t)
{
    int b = blockIdx.x;
    if (b >= g_nb[t]) return;
    int tid = threadIdx.x;
    #pragma unroll
    for (int jj = 0; jj < 2; jj++) {
        int j = tid + jj*256;
        float gi = b_ih[j]        + b_hh[j];
        float gf = b_ih[512 + j]  + b_hh[512 + j];
        float gg = b_ih[1024 + j] + b_hh[1024 + j];
        float go = b_ih[1536 + j] + b_hh[1536 + j];
        #pragma unroll
        for (int ks = 0; ks < GSPLIT; ks++) {
            const float* gp = g_gatesPart + ((size_t)ks*Bb + b)*2048;
            gi += gp[j]; gf += gp[512 + j]; gg += gp[1024 + j]; go += gp[1536 + j];
        }
        float i_ = sigmoidf_(gi);
        float f_ = sigmoidf_(gf);
        float g2 = tanhf(gg);
        float o_ = sigmoidf_(go);
        float c = f_ * g_c[b*DD + j] + i_ * g2;
        float h = o_ * tanhf(c);
        g_c[b*DD + j] = c;
        g_h[b*DD + j] = h;
    }
}

// ------------------- fc partial reduce + bias + masked store -------------------
__global__ void k_fcred(const float* __restrict__ fc_b, float* __restrict__ out, int t)
{
    int b = blockIdx.y;
    if (b >= g_nb[t]) return;
    int n = blockIdx.x*256 + threadIdx.x;
    if (n >= VV) return;
    float v = g_fcPart[(size_t)b*FCLD + n]
            + g_fcPart[(size_t)(Bb + b)*FCLD + n]
            + fc_b[n];
    out[PRED_OFF + (size_t)b*MAXT*VV + (size_t)t*VV + n] = v;
}

// ------------------- host -------------------
extern "C" void kernel_launch(void* const* d_in, const int* in_sizes, int n_in,
                              void* d_out_v, int out_size)
{
    const float* enc   = (const float*)d_in[0];
    const int*   caps  = (const int*)  d_in[1];
    const int*   lens  = (const int*)  d_in[2];
    const float* embT  = (const float*)d_in[3];
    const float* W_a   = (const float*)d_in[4];
    const float* U_a   = (const float*)d_in[5];
    const float* w_att = (const float*)d_in[6];
    const float* fb_W  = (const float*)d_in[7];
    const float* fb_b  = (const float*)d_in[8];
    const float* W_ih  = (const float*)d_in[9];
    const float* W_hh  = (const float*)d_in[10];
    const float* b_ih  = (const float*)d_in[11];
    const float* b_hh  = (const float*)d_in[12];
    const float* fc_W  = (const float*)d_in[13];
    const float* fc_b  = (const float*)d_in[14];
    const float* ih_W  = (const float*)d_in[15];
    const float* ih_b  = (const float*)d_in[16];
    const float* ic_W  = (const float*)d_in[17];
    const float* ic_b  = (const float*)d_in[18];
    float* out = (float*)d_out_v;

    void *pMean, *pH, *pWaEnc, *pWcat, *pHU, *pXcat, *pGates, *pFc, *pInit;
    cudaGetSymbolAddress(&pMean,  g_mean);
    cudaGetSymbolAddress(&pH,     g_h);
    cudaGetSymbolAddress(&pWaEnc, g_WaEnc);
    cudaGetSymbolAddress(&pWcat,  g_Wcat);
    cudaGetSymbolAddress(&pHU,    g_hUpart);
    cudaGetSymbolAddress(&pXcat,  g_xcat);
    cudaGetSymbolAddress(&pGates, g_gatesPart);
    cudaGetSymbolAddress(&pFc,    g_fcPart);
    cudaGetSymbolAddress(&pInit,  g_initPart);

    cudaMemsetAsync(out, 0, (size_t)out_size * sizeof(float), 0);

    k_sort<<<1, 64>>>(lens, caps, out);
    k_wcat<<<2048, 256>>>(W_ih, W_hh);
    k_mean<<<dim3(64,8), 256>>>(enc);

    // h0/c0 partials: 64x512, K=2048, z=16
    gemm2<false,false><<<dim3(4,1,16), 256>>>(
        (const float*)pMean, ih_W, (float*)pInit, 64, 512, 2048, 2048, 512);
    gemm2<false,false><<<dim3(4,1,16), 256>>>(
        (const float*)pMean, ic_W, (float*)pInit + (size_t)16*64*512, 64, 512, 2048, 2048, 512);
    k_init<<<64, 256>>>(ih_b, ic_b);

    // WaEnc = enc[sidx] @ W_a : 12544 x 512, K=2048
    gemm2<false,true><<<dim3(4,196,1), 256>>>(
        enc, W_a, (float*)pWaEnc, 12544, 512, 2048, 2048, 512);

    for (int t = 0; t < MAXT; t++) {
        // hU partials: 64x512, K=512, z=8
        gemm2<false,false><<<dim3(4,1,HSPLIT), 256>>>(
            (const float*)pH, U_a, (float*)pHU, 64, 512, 512, 512, 512);

        k_energy<<<dim3(64,4), 256>>>(caps, embT, fb_W, fb_b, w_att, t);
        k_context<<<dim3(64,8), 256>>>(enc, out, t);

        // gates partials: 64x2048, K=3072 (xcat @ Wcat^T), z=12
        gemm2<true,false><<<dim3(16,1,GSPLIT), 256>>>(
            (const float*)pXcat, (const float*)pWcat, (float*)pGates,
            64, 2048, XK, XK, 2048);

        k_lstm<<<64, 256>>>(b_ih, b_hh, t);

        // fc partials: 64x10000, K=512, z=2
        gemm2<false,false><<<dim3(79,1,2), 256>>>(
            (const float*)pH, fc_W, (float*)pFc, 64, VV, 512, 512, FCLD);
        k_fcred<<<dim3(40,64), 256>>>(fc_b, out, t);
    }
}